// round 2
// baseline (speedup 1.0000x reference)
#include <cuda_runtime.h>

#define NB 16
#define NN 512
#define MU 768
#define GRP 8        // lines per CTA
#define THREADS 128
#define VPT 4        // s-positions per thread (s = t, t+128, t+256, t+384)

// 16 MB scratch for the transposed image (family-1 lines need y-major rows)
__device__ float g_imgT[NB * NN * NN];

__global__ void transpose_kernel(const float* __restrict__ in) {
    __shared__ float tile[32][33];
    const int b = blockIdx.z;
    const float* src = in + (size_t)b * NN * NN;
    float* dst = g_imgT + (size_t)b * NN * NN;
    const int x0 = blockIdx.x * 32, y0 = blockIdx.y * 32;
#pragma unroll
    for (int i = threadIdx.y; i < 32; i += 8)
        tile[i][threadIdx.x] = src[(x0 + i) * NN + (y0 + threadIdx.x)];
    __syncthreads();
#pragma unroll
    for (int i = threadIdx.y; i < 32; i += 8)
        dst[(y0 + i) * NN + (x0 + threadIdx.x)] = tile[threadIdx.x][i];
}

// LDS with compile-time immediate offset (guarantees 1 IADD + 4 LDS per line-group)
template <int IMM>
__device__ __forceinline__ float ldsi(unsigned addr) {
    float v;
    asm volatile("ld.shared.f32 %0, [%1+%2];" : "=f"(v) : "r"(addr), "n"(IMM));
    return v;
}

template <int BUFOFF>
__device__ __forceinline__ void process(unsigned sbase_t, const int* c4,
                                        float acc[GRP][VPT]) {
#pragma unroll
    for (int g = 0; g < GRP; g++) {
        // shared element index = 512 + t - c  (always in [1, 1024) thanks to 2x replication)
        unsigned a = sbase_t - (unsigned)c4[g];
        acc[g][0] += ldsi<BUFOFF + 0>(a);       // s = t
        acc[g][1] += ldsi<BUFOFF + 512>(a);     // s = t + 128
        acc[g][2] += ldsi<BUFOFF + 1024>(a);    // s = t + 256
        acc[g][3] += ldsi<BUFOFF + 1536>(a);    // s = t + 384
    }
}

__global__ __launch_bounds__(THREADS, 6) void drt_main(const float* __restrict__ img,
                                                       float* __restrict__ out) {
    __shared__ float sh[2][1024];   // double-buffered, 2x-replicated image row
    const int t = threadIdx.x;
    const int grp = blockIdx.x;
    const int b = blockIdx.y;

    const float* src;
    int s40, ds4, row0;
    if (grp < NN / GRP) {                       // family 1: m in [0, 512)
        const int m0 = grp * GRP;
        src = g_imgT + (size_t)b * NN * NN;     // sum over y, rows of transposed image
        s40 = 4 * m0; ds4 = 4; row0 = m0;       // c step per y = m (byte units x4)
    } else {                                    // family 2: m = 512 + t0..  (step 2t)
        const int t0 = (grp - NN / GRP) * GRP;
        src = img + (size_t)b * NN * NN;        // sum over x, rows of original image
        s40 = 8 * t0; ds4 = 8; row0 = NN + t0;  // c step per x = 2t
    }

    unsigned shbase;
    asm("{ .reg .u64 u; cvta.to.shared.u64 u, %1; cvt.u32.u64 %0, u; }"
        : "=r"(shbase) : "l"((void*)&sh[0][0]));
    const unsigned sbase_t = shbase + 2048u + 4u * (unsigned)t;  // &sh[buf][512 + t]

    float acc[GRP][VPT];
#pragma unroll
    for (int g = 0; g < GRP; g++)
#pragma unroll
        for (int v = 0; v < VPT; v++) acc[g][v] = 0.f;

    int c4[GRP];   // 4 * ((step_g * y) mod 512), maintained incrementally
#pragma unroll
    for (int g = 0; g < GRP; g++) c4[g] = 0;

    // preload row 0 into buffer 0 (replicated twice)
    float4 v0 = reinterpret_cast<const float4*>(src)[t];
    *reinterpret_cast<float4*>(&sh[0][4 * t]) = v0;
    *reinterpret_cast<float4*>(&sh[0][512 + 4 * t]) = v0;
    __syncthreads();

    for (int y = 0; y < NN; y += 2) {
        const int y1 = (y + 1 < NN) ? y + 1 : NN - 1;
        float4 nv = reinterpret_cast<const float4*>(src + y1 * NN)[t];

        process<0>(sbase_t, c4, acc);           // buffer 0, row y
#pragma unroll
        for (int g = 0; g < GRP; g++) c4[g] = (c4[g] + s40 + g * ds4) & 2047;

        *reinterpret_cast<float4*>(&sh[1][4 * t]) = nv;
        *reinterpret_cast<float4*>(&sh[1][512 + 4 * t]) = nv;
        __syncthreads();

        const int y2 = (y + 2 < NN) ? y + 2 : NN - 1;
        nv = reinterpret_cast<const float4*>(src + y2 * NN)[t];

        process<4096>(sbase_t, c4, acc);        // buffer 1, row y+1
#pragma unroll
        for (int g = 0; g < GRP; g++) c4[g] = (c4[g] + s40 + g * ds4) & 2047;

        *reinterpret_cast<float4*>(&sh[0][4 * t]) = nv;
        *reinterpret_cast<float4*>(&sh[0][512 + 4 * t]) = nv;
        __syncthreads();
    }

    const float SCALE = 0.044194173824159216f;  // 1/sqrt(512)
    float2* o2 = reinterpret_cast<float2*>(out);
#pragma unroll
    for (int g = 0; g < GRP; g++) {
        const int m = row0 + g;
        const long base = ((long)b * MU + m) * NN;
#pragma unroll
        for (int v = 0; v < VPT; v++) {
            const int s = t + 128 * v;
            o2[base + s] = make_float2(acc[g][v] * SCALE, 0.f);
        }
    }
}

extern "C" void kernel_launch(void* const* d_in, const int* in_sizes, int n_in,
                              void* d_out, int out_size) {
    const float* img = (const float*)d_in[0];
    float* out = (float*)d_out;

    dim3 tb(32, 8, 1), tg(NN / 32, NN / 32, NB);
    transpose_kernel<<<tg, tb>>>(img);

    dim3 mg(NN / GRP + (NN / 2) / GRP, NB, 1);  // 64 + 32 = 96 line-groups x 16 batches
    drt_main<<<mg, THREADS>>>(img, out);
}

// round 3
// speedup vs baseline: 3.9323x; 3.9323x over previous
#include <cuda_runtime.h>

#define NN 512
#define NB 16
#define MU 768

// 64 MB scratch: A1 = row-FFT result [b][y][kx]; A2 = full DFT, layout [b][kx][ky]
__device__ float2 g_A1[NB * NN * NN];
__device__ float2 g_A2[NB * NN * NN];

__device__ __forceinline__ float2 cmul(float2 a, float2 b) {
    return make_float2(a.x * b.x - a.y * b.y, a.x * b.y + a.y * b.x);
}

// 256-entry twiddle table: W[r] = exp(sign * 2*pi*i * r / 512)
__device__ __forceinline__ void build_tw(float2* W, float sign, int tid) {
    for (int r = tid; r < 256; r += 128) {
        float th = sign * 6.283185307179586f * (float)r * (1.0f / 512.0f);
        float s, c;
        sincosf(th, &s, &c);
        W[r] = make_float2(c, s);
    }
}

// NF batched 512-point radix-2 Stockham FFTs in shared memory, 128 threads.
// Buffers a,b each hold NF FFTs at stride ST. Returns pointer holding result.
template <int NF, int ST>
__device__ __forceinline__ float2* fft512(float2* a, float2* b, const float2* W,
                                          int tid) {
    float2* src = a;
    float2* dst = b;
    int m = 1;
#pragma unroll
    for (int st = 0; st < 9; st++) {
#pragma unroll
        for (int q = tid; q < NF * 256; q += 128) {
            const int f = q >> 8;
            const int p = q & 255;
            const int k = p & (m - 1);
            const int jm = p - k;                 // j*m: twiddle index
            const float2 x = src[f * ST + p];
            const float2 y = src[f * ST + p + 256];
            const float2 w = W[jm];
            const int o = f * ST + 2 * p - k;
            dst[o] = make_float2(x.x + y.x, x.y + y.y);
            dst[o + m] = cmul(make_float2(x.x - y.x, x.y - y.y), w);
        }
        __syncthreads();
        float2* t = src; src = dst; dst = t;
        m <<= 1;
    }
    return src;
}

// Stage A: forward FFT along x for 4 image rows per CTA. real -> complex.
__global__ __launch_bounds__(128) void fft_rows(const float* __restrict__ img) {
    __shared__ float2 bufA[4 * 516], bufB[4 * 516], W[256];
    const int tid = threadIdx.x;
    const int y0 = blockIdx.x * 4;
    const int b = blockIdx.y;
    build_tw(W, -1.0f, tid);
    const float* src = img + ((size_t)b * NN + y0) * NN;
    for (int i = tid; i < 4 * 512; i += 128) {
        const int f = i >> 9, x = i & 511;
        bufA[f * 516 + x] = make_float2(src[f * NN + x], 0.0f);
    }
    __syncthreads();
    float2* res = fft512<4, 516>(bufA, bufB, W, tid);
    float2* dst = g_A1 + ((size_t)b * NN + y0) * NN;
    for (int i = tid; i < 4 * 512; i += 128) {
        const int f = i >> 9, kx = i & 511;
        dst[f * NN + kx] = res[f * 516 + kx];
    }
}

// Stage B: forward FFT along y for 4 kx-columns per CTA.
// Reads A1[b][y][kx], writes A2[b][kx][ky] (transposed store -> contiguous rows).
__global__ __launch_bounds__(128) void fft_cols() {
    __shared__ float2 bufA[4 * 516], bufB[4 * 516], W[256];
    const int tid = threadIdx.x;
    const int kx0 = blockIdx.x * 4;
    const int b = blockIdx.y;
    build_tw(W, -1.0f, tid);
    const float2* src = g_A1 + (size_t)b * NN * NN;
    for (int i = tid; i < 4 * 512; i += 128) {
        const int f = i & 3, y = i >> 2;            // 4 consecutive lanes = 32B sector
        bufA[f * 516 + y] = src[(size_t)y * NN + kx0 + f];
    }
    __syncthreads();
    float2* res = fft512<4, 516>(bufA, bufB, W, tid);
    float2* dst = g_A2 + ((size_t)b * NN + kx0) * NN;
    for (int i = tid; i < 4 * 512; i += 128) {
        const int f = i >> 9, ky = i & 511;
        dst[f * NN + ky] = res[f * 516 + ky];
    }
}

// Stage C: gather one Fourier slice (line m) and inverse-FFT it.
// dft[u][v] = A2[b][kx=v][ky=u].
//   m <  512: slice[k] = dft[k, k*m mod 512]          -> A2[(k*m&511)*512 + k]
//   m >= 512: slice[k] = dft[2k(m-512) mod 512, k]    -> A2[k*512 + (2k(m-512)&511)]
__global__ __launch_bounds__(128) void gather_ifft(float* __restrict__ out) {
    __shared__ float2 bufA[516], bufB[516], W[256];
    const int tid = threadIdx.x;
    const int m = blockIdx.x;
    const int b = blockIdx.y;
    build_tw(W, 1.0f, tid);                         // conjugate twiddles (inverse)
    const float2* A2 = g_A2 + (size_t)b * NN * NN;
    if (m < NN) {
        for (int k = tid; k < 512; k += 128) {
            const int col = (k * m) & 511;
            bufA[k] = A2[col * NN + k];
        }
    } else {
        const int t2 = m - NN;
        for (int k = tid; k < 512; k += 128) {
            const int ky = (2 * k * t2) & 511;
            bufA[k] = A2[k * NN + ky];
        }
    }
    __syncthreads();
    float2* res = fft512<1, 516>(bufA, bufB, W, tid);
    // scale = (fft2 ortho: 1/N) * (ifft ortho: 1/sqrt(N)) = 1/512^{1.5}
    const float SC = 8.6316745750242931e-5f;
    float2* o = (float2*)out + ((size_t)b * MU + m) * NN;
    for (int s = tid; s < 512; s += 128) {
        const float2 v = res[s];
        o[s] = make_float2(v.x * SC, v.y * SC);
    }
}

extern "C" void kernel_launch(void* const* d_in, const int* in_sizes, int n_in,
                              void* d_out, int out_size) {
    const float* img = (const float*)d_in[0];
    float* out = (float*)d_out;

    fft_rows<<<dim3(NN / 4, NB), 128>>>(img);
    fft_cols<<<dim3(NN / 4, NB), 128>>>();
    gather_ifft<<<dim3(MU, NB), 128>>>(out);
}

// round 4
// speedup vs baseline: 6.7270x; 1.7107x over previous
#include <cuda_runtime.h>

#define NN 512
#define NB 16
#define MU 768

__device__ float2 g_A1[NB * NN * NN];   // row-FFT result [b][y][kx]
__device__ float2 g_A2[NB * NN * NN];   // full DFT      [b][kx][ky]

__device__ __forceinline__ float2 cadd(float2 a, float2 b) { return make_float2(a.x + b.x, a.y + b.y); }
__device__ __forceinline__ float2 csub(float2 a, float2 b) { return make_float2(a.x - b.x, a.y - b.y); }
__device__ __forceinline__ float2 cmul(float2 a, float2 b) {
    return make_float2(a.x * b.x - a.y * b.y, a.x * b.y + a.y * b.x);
}

// bank-conflict-killing swizzle: XOR bits[4:6] into bits[1:3] (involution)
__device__ __forceinline__ int swz(int i) { return i ^ (((i >> 4) & 7) << 1); }

// DFT-8 in registers, DIF (outputs in natural order). CONJ=true -> e^{+2pi i/8}.
template <bool CONJ>
__device__ __forceinline__ void dft8(const float2 a[8], float2 b[8]) {
    const float C = 0.70710678118654752f;
    float2 u0 = cadd(a[0], a[4]), u1 = cadd(a[1], a[5]);
    float2 u2 = cadd(a[2], a[6]), u3 = cadd(a[3], a[7]);
    float2 v0 = csub(a[0], a[4]);
    float2 d1 = csub(a[1], a[5]);
    float2 d2 = csub(a[2], a[6]);
    float2 d3 = csub(a[3], a[7]);
    float2 v1, v2, v3;
    if (!CONJ) {
        v1 = make_float2(C * (d1.x + d1.y), C * (d1.y - d1.x));   // * w8^1
        v2 = make_float2(d2.y, -d2.x);                            // * -i
        v3 = make_float2(C * (d3.y - d3.x), -C * (d3.x + d3.y));  // * w8^3
    } else {
        v1 = make_float2(C * (d1.x - d1.y), C * (d1.x + d1.y));
        v2 = make_float2(-d2.y, d2.x);                            // * +i
        v3 = make_float2(-C * (d3.x + d3.y), C * (d3.x - d3.y));
    }
    // DFT4(u) -> b0,b2,b4,b6
    {
        float2 x0 = cadd(u0, u2), x1 = cadd(u1, u3);
        float2 y0 = csub(u0, u2);
        float2 t = csub(u1, u3);
        float2 y1 = (!CONJ) ? make_float2(t.y, -t.x) : make_float2(-t.y, t.x);
        b[0] = cadd(x0, x1); b[4] = csub(x0, x1);
        b[2] = cadd(y0, y1); b[6] = csub(y0, y1);
    }
    // DFT4(v) -> b1,b3,b5,b7
    {
        float2 x0 = cadd(v0, v2), x1 = cadd(v1, v3);
        float2 y0 = csub(v0, v2);
        float2 t = csub(v1, v3);
        float2 y1 = (!CONJ) ? make_float2(t.y, -t.x) : make_float2(-t.y, t.x);
        b[1] = cadd(x0, x1); b[5] = csub(x0, x1);
        b[3] = cadd(y0, y1); b[7] = csub(y0, y1);
    }
}

// One radix-8 Stockham stage (per-thread, p in [0,64)). M in {1,8,64}.
template <bool CONJ, int M>
__device__ __forceinline__ void do_stage(const float2* src, float2* dst,
                                         const float2* W, int p) {
    float2 a[8];
#pragma unroll
    for (int r = 0; r < 8; r++) a[r] = src[swz(p + 64 * r)];
    float2 b[8];
    dft8<CONJ>(a, b);
    if (M == 64) {                        // j = 0: no twiddles
#pragma unroll
        for (int q = 0; q < 8; q++) dst[swz(p + 64 * q)] = b[q];
    } else {
        const int k = p & (M - 1);
        const int jm = p - k;             // j*M
        float2 w1 = W[jm];
        if (CONJ) w1.y = -w1.y;
        float2 w2 = cmul(w1, w1);
        float2 w3 = cmul(w2, w1);
        float2 w4 = cmul(w2, w2);
        float2 w5 = cmul(w4, w1);
        float2 w6 = cmul(w4, w2);
        float2 w7 = cmul(w4, w3);
        const int base = 8 * jm + k;
        dst[swz(base)]         = b[0];
        dst[swz(base + M)]     = cmul(b[1], w1);
        dst[swz(base + 2 * M)] = cmul(b[2], w2);
        dst[swz(base + 3 * M)] = cmul(b[3], w3);
        dst[swz(base + 4 * M)] = cmul(b[4], w4);
        dst[swz(base + 5 * M)] = cmul(b[5], w5);
        dst[swz(base + 6 * M)] = cmul(b[6], w6);
        dst[swz(base + 7 * M)] = cmul(b[7], w7);
    }
}

// 512-pt FFT: 3 radix-8 stages. Result ends in bufB (swizzled layout).
template <bool CONJ>
__device__ __forceinline__ void run_fft(float2* bufA, float2* bufB,
                                        const float2* W, int p) {
    do_stage<CONJ, 1>(bufA, bufB, W, p);
    __syncthreads();
    do_stage<CONJ, 8>(bufB, bufA, W, p);
    __syncthreads();
    do_stage<CONJ, 64>(bufA, bufB, W, p);
    __syncthreads();
}

__device__ __forceinline__ void build_tw(float2* W, int tid) {
    for (int r = tid; r < 512; r += 256) {
        float s, c;
        sincosf(-6.283185307179586f * (float)r * (1.0f / 512.0f), &s, &c);
        W[r] = make_float2(c, s);
    }
}

// Stage A: forward FFT along x, 4 image rows per CTA (256 threads, 4 FFTs).
__global__ __launch_bounds__(256) void fft_rows(const float* __restrict__ img) {
    __shared__ float2 sA[4 * 512], sB[4 * 512], sW[512];
    const int tid = threadIdx.x, f = tid >> 6, p = tid & 63;
    const int y0 = blockIdx.x * 4, b = blockIdx.y;
    build_tw(sW, tid);
    const float* src = img + ((size_t)b * NN + y0) * NN;
    for (int i = tid; i < 4 * 512; i += 256) {
        const int ff = i >> 9, x = i & 511;
        sA[ff * 512 + swz(x)] = make_float2(src[ff * NN + x], 0.0f);
    }
    __syncthreads();
    run_fft<false>(sA + f * 512, sB + f * 512, sW, p);
    float2* dst = g_A1 + ((size_t)b * NN + y0) * NN;
    for (int i = tid; i < 4 * 512; i += 256) {
        const int ff = i >> 9, kx = i & 511;
        dst[ff * NN + kx] = sB[ff * 512 + swz(kx)];
    }
}

// Stage B: forward FFT along y, 4 kx-columns per CTA; transposed store -> A2[kx][ky].
__global__ __launch_bounds__(256) void fft_cols() {
    __shared__ float2 sA[4 * 512], sB[4 * 512], sW[512];
    const int tid = threadIdx.x, f = tid >> 6, p = tid & 63;
    const int kx0 = blockIdx.x * 4, b = blockIdx.y;
    build_tw(sW, tid);
    const float2* src = g_A1 + (size_t)b * NN * NN;
    for (int i = tid; i < 4 * 512; i += 256) {
        const int c = i & 3, y = i >> 2;        // 4 consecutive lanes = 32B sector
        sA[c * 512 + swz(y)] = src[(size_t)y * NN + kx0 + c];
    }
    __syncthreads();
    run_fft<false>(sA + f * 512, sB + f * 512, sW, p);
    float2* dst = g_A2 + ((size_t)b * NN + kx0) * NN;
    for (int i = tid; i < 4 * 512; i += 256) {
        const int c = i >> 9, ky = i & 511;
        dst[c * NN + ky] = sB[c * 512 + swz(ky)];
    }
}

// Stage C: gather Fourier slice for 4 lines per CTA, inverse-FFT, write output.
//   m <  512: slice[k] = A2[(k*m mod 512)*512 + k]
//   m >= 512: slice[k] = A2[k*512 + (2k(m-512) mod 512)]
__global__ __launch_bounds__(256) void gather_ifft(float* __restrict__ out) {
    __shared__ float2 sA[4 * 512], sB[4 * 512], sW[512];
    const int tid = threadIdx.x, f = tid >> 6, p = tid & 63;
    const int m0 = blockIdx.x * 4, b = blockIdx.y;
    build_tw(sW, tid);
    const float2* A2 = g_A2 + (size_t)b * NN * NN;
    const int m = m0 + f;
    if (m < NN) {
#pragma unroll
        for (int k = p; k < 512; k += 64)
            sA[f * 512 + swz(k)] = A2[((k * m) & 511) * NN + k];
    } else {
        const int t2 = m - NN;
#pragma unroll
        for (int k = p; k < 512; k += 64)
            sA[f * 512 + swz(k)] = A2[k * NN + ((2 * k * t2) & 511)];
    }
    __syncthreads();
    run_fft<true>(sA + f * 512, sB + f * 512, sW, p);
    const float SC = 8.6316745750242931e-5f;    // 1 / 512^1.5
    float2* o = (float2*)out + ((size_t)b * MU + m) * NN;
#pragma unroll
    for (int s = p; s < 512; s += 64) {
        const float2 v = sB[f * 512 + swz(s)];
        o[s] = make_float2(v.x * SC, v.y * SC);
    }
}

extern "C" void kernel_launch(void* const* d_in, const int* in_sizes, int n_in,
                              void* d_out, int out_size) {
    const float* img = (const float*)d_in[0];
    float* out = (float*)d_out;

    fft_rows<<<dim3(NN / 4, NB), 256>>>(img);
    fft_cols<<<dim3(NN / 4, NB), 256>>>();
    gather_ifft<<<dim3(MU / 4, NB), 256>>>(out);
}

// round 5
// speedup vs baseline: 8.3485x; 1.2410x over previous
#include <cuda_runtime.h>

#define NN 512
#define NB 16
#define MU 768

__device__ float2 g_A1[NB * NN * NN];   // row-FFT, only kx<=256 valid  [b][y][kx]
__device__ float2 g_A2[NB * NN * NN];   // half spectrum, kx<=256      [b][kx][ky]
__device__ float2 g_W[512];             // forward twiddles e^{-2pi i r/512}

__device__ __forceinline__ float2 cadd(float2 a, float2 b) { return make_float2(a.x + b.x, a.y + b.y); }
__device__ __forceinline__ float2 csub(float2 a, float2 b) { return make_float2(a.x - b.x, a.y - b.y); }
__device__ __forceinline__ float2 cmul(float2 a, float2 b) {
    return make_float2(a.x * b.x - a.y * b.y, a.x * b.y + a.y * b.x);
}

// bank-conflict-killing swizzle: XOR bits[4:6] into bits[1:3] (involution)
__device__ __forceinline__ int swz(int i) { return i ^ (((i >> 4) & 7) << 1); }

template <bool CONJ>
__device__ __forceinline__ void dft8(const float2 a[8], float2 b[8]) {
    const float C = 0.70710678118654752f;
    float2 u0 = cadd(a[0], a[4]), u1 = cadd(a[1], a[5]);
    float2 u2 = cadd(a[2], a[6]), u3 = cadd(a[3], a[7]);
    float2 v0 = csub(a[0], a[4]);
    float2 d1 = csub(a[1], a[5]);
    float2 d2 = csub(a[2], a[6]);
    float2 d3 = csub(a[3], a[7]);
    float2 v1, v2, v3;
    if (!CONJ) {
        v1 = make_float2(C * (d1.x + d1.y), C * (d1.y - d1.x));
        v2 = make_float2(d2.y, -d2.x);
        v3 = make_float2(C * (d3.y - d3.x), -C * (d3.x + d3.y));
    } else {
        v1 = make_float2(C * (d1.x - d1.y), C * (d1.x + d1.y));
        v2 = make_float2(-d2.y, d2.x);
        v3 = make_float2(-C * (d3.x + d3.y), C * (d3.x - d3.y));
    }
    {
        float2 x0 = cadd(u0, u2), x1 = cadd(u1, u3);
        float2 y0 = csub(u0, u2);
        float2 t = csub(u1, u3);
        float2 y1 = (!CONJ) ? make_float2(t.y, -t.x) : make_float2(-t.y, t.x);
        b[0] = cadd(x0, x1); b[4] = csub(x0, x1);
        b[2] = cadd(y0, y1); b[6] = csub(y0, y1);
    }
    {
        float2 x0 = cadd(v0, v2), x1 = cadd(v1, v3);
        float2 y0 = csub(v0, v2);
        float2 t = csub(v1, v3);
        float2 y1 = (!CONJ) ? make_float2(t.y, -t.x) : make_float2(-t.y, t.x);
        b[1] = cadd(x0, x1); b[5] = csub(x0, x1);
        b[3] = cadd(y0, y1); b[7] = csub(y0, y1);
    }
}

template <bool CONJ, int M>
__device__ __forceinline__ void do_stage(const float2* src, float2* dst,
                                         const float2* W, int p) {
    float2 a[8];
#pragma unroll
    for (int r = 0; r < 8; r++) a[r] = src[swz(p + 64 * r)];
    float2 b[8];
    dft8<CONJ>(a, b);
    if (M == 64) {
#pragma unroll
        for (int q = 0; q < 8; q++) dst[swz(p + 64 * q)] = b[q];
    } else {
        const int k = p & (M - 1);
        const int jm = p - k;
        float2 w1 = W[jm];
        if (CONJ) w1.y = -w1.y;
        float2 w2 = cmul(w1, w1);
        float2 w3 = cmul(w2, w1);
        float2 w4 = cmul(w2, w2);
        float2 w5 = cmul(w4, w1);
        float2 w6 = cmul(w4, w2);
        float2 w7 = cmul(w4, w3);
        const int base = 8 * jm + k;
        dst[swz(base)]         = b[0];
        dst[swz(base + M)]     = cmul(b[1], w1);
        dst[swz(base + 2 * M)] = cmul(b[2], w2);
        dst[swz(base + 3 * M)] = cmul(b[3], w3);
        dst[swz(base + 4 * M)] = cmul(b[4], w4);
        dst[swz(base + 5 * M)] = cmul(b[5], w5);
        dst[swz(base + 6 * M)] = cmul(b[6], w6);
        dst[swz(base + 7 * M)] = cmul(b[7], w7);
    }
}

template <bool CONJ>
__device__ __forceinline__ void run_fft(float2* bufA, float2* bufB,
                                        const float2* W, int p) {
    do_stage<CONJ, 1>(bufA, bufB, W, p);
    __syncthreads();
    do_stage<CONJ, 8>(bufB, bufA, W, p);
    __syncthreads();
    do_stage<CONJ, 64>(bufA, bufB, W, p);
    __syncthreads();
}

__global__ void twiddle_init() {
    const int r = threadIdx.x;
    float s, c;
    sincosf(-6.283185307179586f * (float)r * (1.0f / 512.0f), &s, &c);
    g_W[r] = make_float2(c, s);
}

__device__ __forceinline__ void load_tw(float2* sW, int tid) {
    for (int r = tid; r < 512; r += 256) sW[r] = g_W[r];
}

// Stage A: forward FFT along x for PAIRS of real rows (Z = rowA + i*rowB).
// Untangle and store only kx in [0,256] of A1 (all fft_cols ever reads).
__global__ __launch_bounds__(256) void fft_rows(const float* __restrict__ img) {
    __shared__ float2 sA[4 * 512], sB[4 * 512], sW[512];
    const int tid = threadIdx.x, f = tid >> 6, p = tid & 63;
    const int y0 = blockIdx.x * 8, b = blockIdx.y;   // 4 pairs = 8 rows per CTA
    load_tw(sW, tid);
    const float* src = img + ((size_t)b * NN + y0) * NN;
    for (int i = tid; i < 4 * 512; i += 256) {
        const int ff = i >> 9, x = i & 511;
        sA[ff * 512 + swz(x)] =
            make_float2(src[(2 * ff) * NN + x], src[(2 * ff + 1) * NN + x]);
    }
    __syncthreads();
    run_fft<false>(sA + f * 512, sB + f * 512, sW, p);
    float2* dst = g_A1 + ((size_t)b * NN + y0) * NN;
    // Hermitian untangle: X[k] = (Z[k]+conj(Z[-k]))/2 ; Y[k] = -i(Z[k]-conj(Z[-k]))/2
#pragma unroll
    for (int k = p; k < 257; k += 64) {
        const float2 Zr = sB[f * 512 + swz(k)];
        const float2 Zs = sB[f * 512 + swz((512 - k) & 511)];
        const float2 X = make_float2(0.5f * (Zr.x + Zs.x), 0.5f * (Zr.y - Zs.y));
        const float2 Y = make_float2(0.5f * (Zr.y + Zs.y), 0.5f * (Zs.x - Zr.x));
        dst[(2 * f) * NN + k] = X;
        dst[(2 * f + 1) * NN + k] = Y;
    }
}

// Stage B: forward FFT along y for kx in [0,256] only; store A2[kx][ky].
__global__ __launch_bounds__(256) void fft_cols() {
    __shared__ float2 sA[4 * 512], sB[4 * 512], sW[512];
    const int tid = threadIdx.x, f = tid >> 6, p = tid & 63;
    const int kx0 = blockIdx.x * 4, b = blockIdx.y;
    load_tw(sW, tid);
    const float2* src = g_A1 + (size_t)b * NN * NN;
    for (int i = tid; i < 4 * 512; i += 256) {
        const int c = i & 3, y = i >> 2;
        sA[c * 512 + swz(y)] = src[(size_t)y * NN + kx0 + c];
    }
    __syncthreads();
    run_fft<false>(sA + f * 512, sB + f * 512, sW, p);
    const int kx = kx0 + f;
    if (kx <= 256) {
        float2* dst = g_A2 + ((size_t)b * NN + kx) * NN;
#pragma unroll
        for (int ky = p; ky < 512; ky += 64) dst[ky] = sB[f * 512 + swz(ky)];
    }
}

// Fetch slice[k] of line m from the half spectrum (conjugate mirror for kx>256).
//   m <  512: (kx,ky) = (k*m mod 512, k)
//   m >= 512: (kx,ky) = (k, 2k(m-512) mod 512)
__device__ __forceinline__ float2 slice_elem(const float2* A2, int m, int k) {
    int kx, ky;
    if (m < NN) { kx = (k * m) & 511; ky = k; }
    else        { kx = k; ky = (2 * k * (m - NN)) & 511; }
    if (kx <= 256) return A2[(size_t)kx * NN + ky];
    const float2 v = A2[(size_t)(NN - kx) * NN + ((NN - ky) & 511)];
    return make_float2(v.x, -v.y);
}

// Stage C: slices are Hermitian -> sinogram lines are real. Pack two slices
// per inverse FFT: Z = s1 + i*s2; re -> line m1, im -> line m2. Imag out = 0.
__global__ __launch_bounds__(256) void gather_ifft(float* __restrict__ out) {
    __shared__ float2 sA[4 * 512], sB[4 * 512], sW[512];
    const int tid = threadIdx.x, f = tid >> 6, p = tid & 63;
    const int base = blockIdx.x * 8, b = blockIdx.y;   // 4 pairs = 8 lines per CTA
    load_tw(sW, tid);
    const float2* A2 = g_A2 + (size_t)b * NN * NN;
    const int m1 = base + 2 * f, m2 = m1 + 1;
#pragma unroll
    for (int k = p; k < 512; k += 64) {
        const float2 s1 = slice_elem(A2, m1, k);
        const float2 s2 = slice_elem(A2, m2, k);
        sA[f * 512 + swz(k)] = make_float2(s1.x - s2.y, s1.y + s2.x);
    }
    __syncthreads();
    run_fft<true>(sA + f * 512, sB + f * 512, sW, p);
    const float SC = 8.6316745750242931e-5f;    // 1 / 512^1.5
    float2* o1 = (float2*)out + ((size_t)b * MU + m1) * NN;
    float2* o2 = (float2*)out + ((size_t)b * MU + m2) * NN;
#pragma unroll
    for (int s = p; s < 512; s += 64) {
        const float2 v = sB[f * 512 + swz(s)];
        o1[s] = make_float2(v.x * SC, 0.0f);
        o2[s] = make_float2(v.y * SC, 0.0f);
    }
}

extern "C" void kernel_launch(void* const* d_in, const int* in_sizes, int n_in,
                              void* d_out, int out_size) {
    const float* img = (const float*)d_in[0];
    float* out = (float*)d_out;

    twiddle_init<<<1, 512>>>();
    fft_rows<<<dim3(NN / 8, NB), 256>>>(img);
    fft_cols<<<dim3(65, NB), 256>>>();          // kx 0..259, guarded at 256
    gather_ifft<<<dim3(MU / 8, NB), 256>>>(out);
}

// round 6
// speedup vs baseline: 9.6003x; 1.1499x over previous
#include <cuda_runtime.h>

#define NN 512
#define NB 16
#define MU 768

__device__ float2 g_A1[NB * NN * NN];   // row-FFT, only kx<=256 valid  [b][y][kx]
__device__ float2 g_A2[NB * NN * NN];   // half spectrum, kx<=256      [b][kx][ky]
__device__ float2 g_W[512];             // forward twiddles e^{-2pi i r/512}

__device__ __forceinline__ float2 cadd(float2 a, float2 b) { return make_float2(a.x + b.x, a.y + b.y); }
__device__ __forceinline__ float2 csub(float2 a, float2 b) { return make_float2(a.x - b.x, a.y - b.y); }
__device__ __forceinline__ float2 cmul(float2 a, float2 b) {
    return make_float2(a.x * b.x - a.y * b.y, a.x * b.y + a.y * b.x);
}

// bank-conflict-killing swizzle: XOR bits[4:6] into bits[1:3] (involution)
__device__ __forceinline__ int swz(int i) { return i ^ (((i >> 4) & 7) << 1); }

// per-FFT-unit barrier: 64 threads (2 warps), named barrier id in [1,4]
__device__ __forceinline__ void bar64(int id) {
    asm volatile("bar.sync %0, 64;" :: "r"(id) : "memory");
}

template <bool CONJ>
__device__ __forceinline__ void dft8(const float2 a[8], float2 b[8]) {
    const float C = 0.70710678118654752f;
    float2 u0 = cadd(a[0], a[4]), u1 = cadd(a[1], a[5]);
    float2 u2 = cadd(a[2], a[6]), u3 = cadd(a[3], a[7]);
    float2 v0 = csub(a[0], a[4]);
    float2 d1 = csub(a[1], a[5]);
    float2 d2 = csub(a[2], a[6]);
    float2 d3 = csub(a[3], a[7]);
    float2 v1, v2, v3;
    if (!CONJ) {
        v1 = make_float2(C * (d1.x + d1.y), C * (d1.y - d1.x));
        v2 = make_float2(d2.y, -d2.x);
        v3 = make_float2(C * (d3.y - d3.x), -C * (d3.x + d3.y));
    } else {
        v1 = make_float2(C * (d1.x - d1.y), C * (d1.x + d1.y));
        v2 = make_float2(-d2.y, d2.x);
        v3 = make_float2(-C * (d3.x + d3.y), C * (d3.x - d3.y));
    }
    {
        float2 x0 = cadd(u0, u2), x1 = cadd(u1, u3);
        float2 y0 = csub(u0, u2);
        float2 t = csub(u1, u3);
        float2 y1 = (!CONJ) ? make_float2(t.y, -t.x) : make_float2(-t.y, t.x);
        b[0] = cadd(x0, x1); b[4] = csub(x0, x1);
        b[2] = cadd(y0, y1); b[6] = csub(y0, y1);
    }
    {
        float2 x0 = cadd(v0, v2), x1 = cadd(v1, v3);
        float2 y0 = csub(v0, v2);
        float2 t = csub(v1, v3);
        float2 y1 = (!CONJ) ? make_float2(t.y, -t.x) : make_float2(-t.y, t.x);
        b[1] = cadd(x0, x1); b[5] = csub(x0, x1);
        b[3] = cadd(y0, y1); b[7] = csub(y0, y1);
    }
}

template <bool CONJ, int M>
__device__ __forceinline__ void do_stage(const float2* src, float2* dst,
                                         const float2* W, int p) {
    float2 a[8];
#pragma unroll
    for (int r = 0; r < 8; r++) a[r] = src[swz(p + 64 * r)];
    float2 b[8];
    dft8<CONJ>(a, b);
    if (M == 64) {
#pragma unroll
        for (int q = 0; q < 8; q++) dst[swz(p + 64 * q)] = b[q];
    } else {
        const int k = p & (M - 1);
        const int jm = p - k;
        float2 w1 = W[jm];
        if (CONJ) w1.y = -w1.y;
        float2 w2 = cmul(w1, w1);
        float2 w3 = cmul(w2, w1);
        float2 w4 = cmul(w2, w2);
        float2 w5 = cmul(w4, w1);
        float2 w6 = cmul(w4, w2);
        float2 w7 = cmul(w4, w3);
        const int base = 8 * jm + k;
        dst[swz(base)]         = b[0];
        dst[swz(base + M)]     = cmul(b[1], w1);
        dst[swz(base + 2 * M)] = cmul(b[2], w2);
        dst[swz(base + 3 * M)] = cmul(b[3], w3);
        dst[swz(base + 4 * M)] = cmul(b[4], w4);
        dst[swz(base + 5 * M)] = cmul(b[5], w5);
        dst[swz(base + 6 * M)] = cmul(b[6], w6);
        dst[swz(base + 7 * M)] = cmul(b[7], w7);
    }
}

// 512-pt FFT: 3 radix-8 stages, per-unit named barriers (64 threads/unit).
template <bool CONJ>
__device__ __forceinline__ void run_fft(float2* bufA, float2* bufB,
                                        const float2* W, int p, int bid) {
    do_stage<CONJ, 1>(bufA, bufB, W, p);
    bar64(bid);
    do_stage<CONJ, 8>(bufB, bufA, W, p);
    bar64(bid);
    do_stage<CONJ, 64>(bufA, bufB, W, p);
    bar64(bid);
}

__global__ void twiddle_init() {
    const int r = threadIdx.x;
    float s, c;
    sincosf(-6.283185307179586f * (float)r * (1.0f / 512.0f), &s, &c);
    g_W[r] = make_float2(c, s);
}

__device__ __forceinline__ void load_tw(float2* sW, int tid) {
    for (int r = tid; r < 512; r += 256) sW[r] = g_W[r];
}

// Stage A: forward FFT along x for PAIRS of real rows (Z = rowA + i*rowB).
// Untangle; store only kx in [0,256] of A1 (all fft_cols ever reads).
__global__ __launch_bounds__(256) void fft_rows(const float* __restrict__ img) {
    __shared__ float2 sA[4 * 512], sB[4 * 512], sW[512];
    const int tid = threadIdx.x, f = tid >> 6, p = tid & 63;
    const int y0 = blockIdx.x * 8, b = blockIdx.y;   // 4 pairs = 8 rows per CTA
    load_tw(sW, tid);
    const float* src = img + ((size_t)b * NN + y0) * NN;
    for (int i = tid; i < 4 * 512; i += 256) {
        const int ff = i >> 9, x = i & 511;
        sA[ff * 512 + swz(x)] =
            make_float2(src[(2 * ff) * NN + x], src[(2 * ff + 1) * NN + x]);
    }
    __syncthreads();
    run_fft<false>(sA + f * 512, sB + f * 512, sW, p, 1 + f);
    float2* dst = g_A1 + ((size_t)b * NN + y0) * NN;
    // Hermitian untangle: X[k] = (Z[k]+conj(Z[-k]))/2 ; Y[k] = -i(Z[k]-conj(Z[-k]))/2
#pragma unroll
    for (int k = p; k < 257; k += 64) {
        const float2 Zr = sB[f * 512 + swz(k)];
        const float2 Zs = sB[f * 512 + swz((512 - k) & 511)];
        const float2 X = make_float2(0.5f * (Zr.x + Zs.x), 0.5f * (Zr.y - Zs.y));
        const float2 Y = make_float2(0.5f * (Zr.y + Zs.y), 0.5f * (Zs.x - Zr.x));
        dst[(2 * f) * NN + k] = X;
        dst[(2 * f + 1) * NN + k] = Y;
    }
}

// Stage B: forward FFT along y for kx in [0,256] only; store A2[kx][ky].
__global__ __launch_bounds__(256) void fft_cols() {
    __shared__ float2 sA[4 * 512], sB[4 * 512], sW[512];
    const int tid = threadIdx.x, f = tid >> 6, p = tid & 63;
    const int kx0 = blockIdx.x * 4, b = blockIdx.y;
    load_tw(sW, tid);
    const float2* src = g_A1 + (size_t)b * NN * NN;
    for (int i = tid; i < 4 * 512; i += 256) {
        const int c = i & 3, y = i >> 2;
        sA[c * 512 + swz(y)] = src[(size_t)y * NN + kx0 + c];
    }
    __syncthreads();
    run_fft<false>(sA + f * 512, sB + f * 512, sW, p, 1 + f);
    const int kx = kx0 + f;
    if (kx <= 256) {
        float2* dst = g_A2 + ((size_t)b * NN + kx) * NN;
#pragma unroll
        for (int ky = p; ky < 512; ky += 64) dst[ky] = sB[f * 512 + swz(ky)];
    }
}

// Fetch slice[k] of line m from the half spectrum (conjugate mirror for kx>256).
//   m <  512: (kx,ky) = (k*m mod 512, k)
//   m >= 512: (kx,ky) = (k, 2k(m-512) mod 512)   [kx<=256 always for k<=256]
__device__ __forceinline__ float2 slice_elem(const float2* A2, int m, int k) {
    int kx, ky;
    if (m < NN) { kx = (k * m) & 511; ky = k; }
    else        { kx = k; ky = (2 * k * (m - NN)) & 511; }
    if (kx <= 256) return A2[(size_t)kx * NN + ky];
    const float2 v = A2[(size_t)(NN - kx) * NN + ((NN - ky) & 511)];
    return make_float2(v.x, -v.y);
}

// Stage C: slices are Hermitian (s[512-k] = conj(s[k])): gather only k<=256,
// mirror-fill the rest in smem. Two slices packed per inverse FFT:
// Z = s1 + i*s2 -> re = line m1, im = line m2. Imag output exact 0.
__global__ __launch_bounds__(256) void gather_ifft(float* __restrict__ out) {
    __shared__ float2 sA[4 * 512], sB[4 * 512], sW[512];
    const int tid = threadIdx.x, f = tid >> 6, p = tid & 63;
    const int base = blockIdx.x * 8, b = blockIdx.y;   // 4 pairs = 8 lines per CTA
    load_tw(sW, tid);
    const float2* A2 = g_A2 + (size_t)b * NN * NN;
    const int m1 = base + 2 * f, m2 = m1 + 1;
#pragma unroll
    for (int k = p; k <= 256; k += 64) {
        const float2 s1 = slice_elem(A2, m1, k);
        const float2 s2 = slice_elem(A2, m2, k);
        sA[f * 512 + swz(k)] = make_float2(s1.x - s2.y, s1.y + s2.x);
        if (k > 0 && k < 256)   // mirror: Z[512-k] = conj(s1) + i*conj(s2)
            sA[f * 512 + swz(512 - k)] =
                make_float2(s1.x + s2.y, s2.x - s1.y);
    }
    __syncthreads();
    run_fft<true>(sA + f * 512, sB + f * 512, sW, p, 1 + f);
    const float SC = 8.6316745750242931e-5f;    // 1 / 512^1.5
    float2* o1 = (float2*)out + ((size_t)b * MU + m1) * NN;
    float2* o2 = (float2*)out + ((size_t)b * MU + m2) * NN;
#pragma unroll
    for (int s = p; s < 512; s += 64) {
        const float2 v = sB[f * 512 + swz(s)];
        o1[s] = make_float2(v.x * SC, 0.0f);
        o2[s] = make_float2(v.y * SC, 0.0f);
    }
}

extern "C" void kernel_launch(void* const* d_in, const int* in_sizes, int n_in,
                              void* d_out, int out_size) {
    const float* img = (const float*)d_in[0];
    float* out = (float*)d_out;

    twiddle_init<<<1, 512>>>();
    fft_rows<<<dim3(NN / 8, NB), 256>>>(img);
    fft_cols<<<dim3(65, NB), 256>>>();          // kx 0..259, guarded at 256
    gather_ifft<<<dim3(MU / 8, NB), 256>>>(out);
}